// round 15
// baseline (speedup 1.0000x reference)
#include <cuda_runtime.h>
#include <cuda_fp16.h>
#include <cstdint>
#include <stdint.h>
#include <math.h>

#define D_DIM 1024
#define B_DIM 8
#define T_DIM 1024
#define L_CH 8
#define DD (1024*1024)
#define SPECTRAL_RADIUS 0.999f
#define EPS_F 1e-8f

// GEMM tiling: CTA tile 64(M) x 128(N), K-chunk 32, 4-stage pipeline.
#define MT 64
#define NT 128
#define KC 32
#define RB 80                               // smem row bytes (40 fp16, pad 8)
#define A_BYTES (MT * RB)                   // 5120
#define B_BYTES (NT * RB)                   // 10240
#define STAGE_BYTES (2 * A_BYTES + 2 * B_BYTES)  // 30720
#define NSTAGE 4
#define GEMM_SMEM (NSTAGE * STAGE_BYTES)    // 122880

// ------------------------- device scratch ------------------------------------
__device__ float g_p[6][D_DIM];
__device__ float g_scale;
__device__ int   g_psync[8];
__device__ __align__(256) __half g_Wh[DD], g_Wl[DD], g_WTh[DD], g_WTl[DD];
__device__ __align__(256) __half g_P0h[DD], g_P0l[DD], g_P0Th[DD], g_P0Tl[DD];
__device__ __align__(256) __half g_P1h[DD], g_P1l[DD], g_P1Th[DD], g_P1Tl[DD];
__device__ __align__(256) __half g_X0[DD], g_X1[DD];
__device__ __align__(256) float g_S[2][DD];

// ------------------------- PTX helpers ---------------------------------------
__device__ __forceinline__ unsigned smem_u32(const void* p) {
    unsigned a;
    asm("{ .reg .u64 t; cvta.to.shared.u64 t, %1; cvt.u32.u64 %0, t; }" : "=r"(a) : "l"(p));
    return a;
}
__device__ __forceinline__ void cp16(unsigned sa, const void* g) {
    asm volatile("cp.async.cg.shared.global [%0], [%1], 16;" :: "r"(sa), "l"(g));
}
__device__ __forceinline__ void cp16z(unsigned sa, const void* g, int srcsize) {
    asm volatile("cp.async.cg.shared.global [%0], [%1], 16, %2;"
                 :: "r"(sa), "l"(g), "r"(srcsize));
}
__device__ __forceinline__ void cp_commit() { asm volatile("cp.async.commit_group;"); }
__device__ __forceinline__ void cp_wait0()  { asm volatile("cp.async.wait_group 0;" ::: "memory"); }
__device__ __forceinline__ void cp_wait1()  { asm volatile("cp.async.wait_group 1;" ::: "memory"); }
__device__ __forceinline__ void cp_wait2()  { asm volatile("cp.async.wait_group 2;" ::: "memory"); }

__device__ __forceinline__ void ldsm4(unsigned addr, unsigned* r) {
    asm volatile("ldmatrix.sync.aligned.m8n8.x4.shared.b16 {%0,%1,%2,%3}, [%4];"
                 : "=r"(r[0]), "=r"(r[1]), "=r"(r[2]), "=r"(r[3]) : "r"(addr));
}
__device__ __forceinline__ void mma16816(float* c, const unsigned* a,
                                         unsigned b0, unsigned b1) {
    asm volatile(
        "mma.sync.aligned.m16n8k16.row.col.f32.f16.f16.f32 "
        "{%0,%1,%2,%3}, {%4,%5,%6,%7}, {%8,%9}, {%0,%1,%2,%3};"
        : "+f"(c[0]), "+f"(c[1]), "+f"(c[2]), "+f"(c[3])
        : "r"(a[0]), "r"(a[1]), "r"(a[2]), "r"(a[3]), "r"(b0), "r"(b1));
}

// ------------------------- fused power iteration ------------------------------
// 6 matvecs (alternating W^T, W) + norm chain in ONE kernel.
// Grid MUST be 128 CTAs x 256 threads; flag-based grid sync between phases.
__global__ void __launch_bounds__(256, 1)
powiter_kernel(const float* __restrict__ W, const float* __restrict__ u) {
    int tid = threadIdx.x, wid = tid >> 5, lane = tid & 31;
    int outIdx = blockIdx.x * 8 + wid;

    for (int p = 0; p < 6; p++) {
        const float* vin = (p == 0) ? u : g_p[p - 1];
        float acc = 0.f;
        if ((p & 1) == 0) {            // W^T * vin
            for (int e = lane; e < D_DIM; e += 32)
                acc += W[(size_t)e * D_DIM + outIdx] * vin[e];
        } else {                        // W * vin
            const float* row = W + (size_t)outIdx * D_DIM;
            for (int d = lane; d < D_DIM; d += 32)
                acc += row[d] * vin[d];
        }
        #pragma unroll
        for (int o = 16; o; o >>= 1) acc += __shfl_down_sync(0xffffffffu, acc, o);
        if (lane == 0) g_p[p][outIdx] = acc;
        // grid sync
        __syncthreads();
        if (tid == 0) {
            __threadfence();
            atomicAdd(&g_psync[p], 1);
            while (*(volatile int*)&g_psync[p] < 128) { }
            __threadfence();
        }
        __syncthreads();
    }

    if (blockIdx.x == 0) {
        __shared__ float red[256];
        __shared__ float ssq[6];
        for (int v = 0; v < 6; v++) {
            float local = 0.f;
            for (int i = tid; i < D_DIM; i += 256) { float x = g_p[v][i]; local += x * x; }
            red[tid] = local;
            __syncthreads();
            for (int s = 128; s; s >>= 1) { if (tid < s) red[tid] += red[tid + s]; __syncthreads(); }
            if (tid == 0) ssq[v] = red[0];
            __syncthreads();
        }
        if (tid == 0) {
            float a1 = 1.f / (sqrtf(ssq[0]) + EPS_F);
            float b1 = a1 / (a1 * sqrtf(ssq[1]) + EPS_F);
            float a2 = b1 / (b1 * sqrtf(ssq[2]) + EPS_F);
            float b2 = a2 / (a2 * sqrtf(ssq[3]) + EPS_F);
            float a3 = b2 / (b2 * sqrtf(ssq[4]) + EPS_F);
            float b3 = a3 / (a3 * sqrtf(ssq[5]) + EPS_F);
            float sigma = fabsf(a3 * b3 * ssq[5]);
            g_scale = SPECTRAL_RADIUS / (sigma + EPS_F);
        }
    }
}

// --------------------- W split (+ transpose), scaled ---------------------------
__global__ void split_tr_kernel(const float* __restrict__ in,
                                __half* __restrict__ oh, __half* __restrict__ ol,
                                __half* __restrict__ oth, __half* __restrict__ otl) {
    __shared__ float tile[32][33];
    float s = g_scale;
    int bx = blockIdx.x, by = blockIdx.y;
    int tx = threadIdx.x, ty = threadIdx.y;     // 32 x 8
    #pragma unroll
    for (int k = 0; k < 4; k++) {
        int r = by * 32 + ty + k * 8, c = bx * 32 + tx;
        float v = in[(size_t)r * D_DIM + c] * s;
        tile[ty + k * 8][tx] = v;
        __half h = __float2half(v);
        oh[(size_t)r * D_DIM + c] = h;
        ol[(size_t)r * D_DIM + c] = __float2half(v - __half2float(h));
    }
    __syncthreads();
    #pragma unroll
    for (int k = 0; k < 4; k++) {
        int rt = bx * 32 + ty + k * 8, ct = by * 32 + tx;
        float v = tile[tx][ty + k * 8];
        __half h = __float2half(v);
        oth[(size_t)rt * D_DIM + ct] = h;
        otl[(size_t)rt * D_DIM + ct] = __float2half(v - __half2float(h));
    }
}

// ------------------------- prep for phase-1 j=0 -------------------------------
__global__ void prep1_kernel(const float* __restrict__ x, const float* __restrict__ h0,
                             __half* __restrict__ a) {
    size_t gid = (size_t)blockIdx.x * 256 + threadIdx.x;
    int m = (int)(gid >> 10), d = (int)(gid & 1023);
    int c = m >> 3, b = m & 7;
    int t = c * L_CH;
    float v = x[((size_t)t * B_DIM + b) * D_DIM + d];
    if (c == 0) v += h0[(size_t)b * D_DIM + d];
    a[gid] = __float2half(v);
}

// ------------------------- job descriptor -------------------------------------
struct Job {
    const __half* Ah; const __half* Al;
    const __half* Bh; const __half* Bl;
    float* out; const float* addsrc; const float* bias; const float* xnext;
    __half* sh; float* fdst;
    __half* ph; __half* pl; __half* pth; __half* ptl;
    int ashift; int emode; int jstep;
};
// emodes:
// 0: out = R (+addsrc); optional sh = half(R). Copy fast-path for fully-shifted tiles.
// 1: phase1: v+=bias; out_h[slot]=v; sh=half(v + xnext[slot]) (or half(v)); fdst opt.
// 2: phase3: out_h[slot]+=v; silu -> fdst; optional sh=half(v).
// 3: squaring: ph/pl direct; pth/ptl via smem transpose. No fp32 out.

// ------------------------- mma.sync fp16 GEMM body ----------------------------
template<int HASAL>
__device__ __forceinline__ void load_chunk(unsigned smb, int stage, const Job& J,
                                           int arow0, int col0, int kc, int tid) {
    unsigned sb = smb + stage * STAGE_BYTES;
    #pragma unroll
    for (int i = 0; i < (HASAL ? 2 : 1); i++) {
        int e = tid + i * 256;
        int arr = e >> 8;
        int rr = (e & 255) >> 2;
        int cc = e & 3;
        const __half* src = arr ? J.Al : J.Ah;
        int r = arow0 + rr + J.ashift;
        int sz = (r >= 0) ? 16 : 0;
        if (r < 0) r = 0;
        cp16z(sb + arr * A_BYTES + rr * RB + cc * 16,
              src + (size_t)r * D_DIM + kc * KC + cc * 8, sz);
    }
    #pragma unroll
    for (int i = 0; i < 4; i++) {
        int e = tid + i * 256;
        int arr = e >> 9;
        int rr = (e & 511) >> 2;
        int cc = e & 3;
        const __half* src = arr ? J.Bl : J.Bh;
        cp16(sb + 2 * A_BYTES + arr * B_BYTES + rr * RB + cc * 16,
             src + (size_t)(col0 + rr) * D_DIM + kc * KC + cc * 8);
    }
    cp_commit();
}

template<int HASAL>
__device__ void gemm_body(const Job J) {
    extern __shared__ char sm[];
    unsigned smb = smem_u32(sm);
    const int tid = threadIdx.x;
    const int wid = tid >> 5, lane = tid & 31;
    const int bx = blockIdx.x, by = blockIdx.y;
    const int warp_m = wid >> 2, warp_n = wid & 3;
    const int g = lane >> 2, tg = lane & 3;

    const int arow0 = by * MT, col0 = bx * NT;

    // Copy fast path: entire tile below shift boundary -> R = 0, out = addsrc.
    if (J.emode == 0 && J.ashift != 0 && arow0 + MT <= -J.ashift) {
        #pragma unroll 4
        for (int i = 0; i < 16; i++) {
            int e = tid + i * 256;            // 4096 float2 per tile
            int r = e >> 6, c2 = e & 63;
            size_t flat = (size_t)(arow0 + r) * D_DIM + col0 + c2 * 2;
            float2 v = *(const float2*)(J.addsrc + flat);
            *(float2*)(J.out + flat) = v;
            if (J.sh) *(__half2*)(J.sh + flat) = __floats2half2_rn(v.x, v.y);
        }
        return;
    }

    unsigned lrow = lane & 15, lhalf = lane >> 4;
    unsigned aBase = smb + (warp_m * 32 + lrow) * RB + lhalf * 16;
    unsigned bBase = smb + 2 * A_BYTES + (warp_n * 32 + lrow) * RB + lhalf * 16;

    float acc[2][4][4];
    #pragma unroll
    for (int i = 0; i < 2; i++)
        #pragma unroll
        for (int j = 0; j < 4; j++)
            #pragma unroll
            for (int q = 0; q < 4; q++) acc[i][j][q] = 0.f;

    const int NKC = D_DIM / KC;   // 32
    #pragma unroll
    for (int s = 0; s < NSTAGE - 1; s++)
        load_chunk<HASAL>(smb, s, J, arow0, col0, s, tid);

    for (int kc = 0; kc < NKC; kc++) {
        int st = kc & (NSTAGE - 1);
        int remain = NKC - 1 - kc;
        if (remain >= 2) cp_wait2();
        else if (remain == 1) cp_wait1();
        else cp_wait0();
        __syncthreads();
        if (kc + NSTAGE - 1 < NKC)
            load_chunk<HASAL>(smb, (kc + NSTAGE - 1) & (NSTAGE - 1),
                              J, arow0, col0, kc + NSTAGE - 1, tid);

        unsigned sa = aBase + st * STAGE_BYTES;
        unsigned sb = bBase + st * STAGE_BYTES;
        #pragma unroll
        for (int ks = 0; ks < 2; ks++) {
            unsigned ko = ks * 32;
            unsigned AH0[4], AH1[4];
            ldsm4(sa + ko, AH0);
            ldsm4(sa + 16 * RB + ko, AH1);
            unsigned AL0[4], AL1[4];
            if (HASAL) {
                ldsm4(sa + A_BYTES + ko, AL0);
                ldsm4(sa + A_BYTES + 16 * RB + ko, AL1);
            }
            unsigned BH0[4], BH1[4], BL0[4], BL1[4];
            ldsm4(sb + ko, BH0);
            ldsm4(sb + 16 * RB + ko, BH1);
            ldsm4(sb + B_BYTES + ko, BL0);
            ldsm4(sb + B_BYTES + 16 * RB + ko, BL1);

            unsigned bh[4][2] = {{BH0[0],BH0[2]},{BH0[1],BH0[3]},
                                 {BH1[0],BH1[2]},{BH1[1],BH1[3]}};
            unsigned bl[4][2] = {{BL0[0],BL0[2]},{BL0[1],BL0[3]},
                                 {BL1[0],BL1[2]},{BL1[1],BL1[3]}};
            #pragma unroll
            for (int j = 0; j < 4; j++) {
                mma16816(acc[0][j], AH0, bh[j][0], bh[j][1]);
                mma16816(acc[0][j], AH0, bl[j][0], bl[j][1]);
                if (HASAL) mma16816(acc[0][j], AL0, bh[j][0], bh[j][1]);
                mma16816(acc[1][j], AH1, bh[j][0], bh[j][1]);
                mma16816(acc[1][j], AH1, bl[j][0], bl[j][1]);
                if (HASAL) mma16816(acc[1][j], AL1, bh[j][0], bh[j][1]);
            }
        }
    }

    // ---------------- Epilogues ----------------
    if (J.emode == 3) {
        // squaring: ph/pl direct + pth/ptl via smem transpose
        __syncthreads();                        // smem free for reuse
        float* ts = (float*)sm;                 // [128 cols][66 rows]
        #pragma unroll
        for (int i = 0; i < 2; i++) {
            #pragma unroll
            for (int j = 0; j < 4; j++) {
                int rl_base = warp_m * 32 + i * 16 + g;
                int cl = warp_n * 32 + j * 8 + tg * 2;
                #pragma unroll
                for (int half = 0; half < 2; half++) {
                    int rl = rl_base + half * 8;
                    float vx = acc[i][j][half * 2 + 0];
                    float vy = acc[i][j][half * 2 + 1];
                    size_t flat = (size_t)(arow0 + rl) * D_DIM + col0 + cl;
                    __half hx = __float2half(vx);
                    __half hy = __float2half(vy);
                    __half2 h2; h2.x = hx; h2.y = hy;
                    __half2 l2;
                    l2.x = __float2half(vx - __half2float(hx));
                    l2.y = __float2half(vy - __half2float(hy));
                    *(__half2*)(J.ph + flat) = h2;
                    *(__half2*)(J.pl + flat) = l2;
                    ts[cl * 66 + rl] = vx;
                    ts[(cl + 1) * 66 + rl] = vy;
                }
            }
        }
        __syncthreads();
        // PT: warp w covers 16 columns; each lane handles row pair
        #pragma unroll
        for (int c16 = 0; c16 < 16; c16++) {
            int cl = wid * 16 + c16;
            float v0 = ts[cl * 66 + 2 * lane];
            float v1 = ts[cl * 66 + 2 * lane + 1];
            __half h0 = __float2half(v0), h1 = __float2half(v1);
            __half2 h2; h2.x = h0; h2.y = h1;
            __half2 l2;
            l2.x = __float2half(v0 - __half2float(h0));
            l2.y = __float2half(v1 - __half2float(h1));
            size_t off = (size_t)(col0 + cl) * D_DIM + arow0 + 2 * lane;
            *(__half2*)(J.pth + off) = h2;
            *(__half2*)(J.ptl + off) = l2;
        }
        return;
    }

    #pragma unroll
    for (int i = 0; i < 2; i++) {
        #pragma unroll
        for (int j = 0; j < 4; j++) {
            int rm = arow0 + warp_m * 32 + i * 16 + g;
            int col = col0 + warp_n * 32 + j * 8 + tg * 2;
            #pragma unroll
            for (int half = 0; half < 2; half++) {
                int r = rm + half * 8;
                float vx = acc[i][j][half * 2 + 0];
                float vy = acc[i][j][half * 2 + 1];
                size_t flat = (size_t)r * D_DIM + col;
                if (J.emode == 0) {
                    if (J.addsrc) {
                        float2 a2 = *(const float2*)(J.addsrc + flat);
                        vx += a2.x; vy += a2.y;
                    }
                    float2 o; o.x = vx; o.y = vy;
                    *(float2*)(J.out + flat) = o;
                    if (J.sh)
                        *(__half2*)(J.sh + flat) = __floats2half2_rn(vx, vy);
                } else {
                    int c = r >> 3, b = r & 7;
                    int t1 = c * L_CH + J.jstep + 1;
                    size_t idx = ((size_t)t1 * B_DIM + b) * D_DIM + col;
                    if (J.emode == 1) {
                        float2 b2 = *(const float2*)(J.bias + col);
                        vx += b2.x; vy += b2.y;
                        float2 o; o.x = vx; o.y = vy;
                        *(float2*)(J.out + idx) = o;
                        if (J.fdst) { float2 f; f.x = vx; f.y = vy;
                                      *(float2*)(J.fdst + flat) = f; }
                        float sx = vx, sy = vy;
                        if (J.xnext) {
                            float2 xv = *(const float2*)(J.xnext + idx);
                            sx += xv.x; sy += xv.y;
                        }
                        *(__half2*)(J.sh + flat) = __floats2half2_rn(sx, sy);
                    } else {  // emode == 2: accumulate + fused silu
                        float2 o = *(const float2*)(J.out + idx);
                        o.x += vx; o.y += vy;
                        *(float2*)(J.out + idx) = o;
                        float2 sv;
                        sv.x = o.x / (1.f + expf(-o.x));
                        sv.y = o.y / (1.f + expf(-o.y));
                        *(float2*)(J.fdst + idx - (size_t)B_DIM * D_DIM) = sv;
                        if (J.sh)
                            *(__half2*)(J.sh + flat) = __floats2half2_rn(vx, vy);
                    }
                }
            }
        }
    }
}

template<int H>
__global__ void __launch_bounds__(256, 1) gemm_solo(const Job j0) {
    gemm_body<H>(j0);
}
template<int H0, int H1>
__global__ void __launch_bounds__(256, 1) gemm_dual(const Job j0, const Job j1) {
    if (blockIdx.z == 0) gemm_body<H0>(j0);
    else                 gemm_body<H1>(j1);
}

// ------------------------------- launcher ------------------------------------
extern "C" void kernel_launch(void* const* d_in, const int* in_sizes, int n_in,
                              void* d_out, int out_size) {
    const float* x  = (const float*)d_in[0];
    const float* h0 = (const float*)d_in[1];
    const float* W  = (const float*)d_in[2];
    const float* bv = (const float*)d_in[3];
    const float* u  = (const float*)d_in[4];

    float* out_silu = (float*)d_out;
    float* out_h    = (float*)d_out + (size_t)T_DIM * B_DIM * D_DIM;  // h[0..T]

    float *S0, *S1; void* psync;
    __half *Wh, *Wl, *WTh, *WTl, *X0, *X1;
    __half *Pb[2][4];   // [buf][h,l,th,tl]
    cudaGetSymbolAddress((void**)&S0, g_S);   S1 = S0 + DD;
    cudaGetSymbolAddress(&psync, g_psync);
    cudaGetSymbolAddress((void**)&Wh, g_Wh);   cudaGetSymbolAddress((void**)&Wl, g_Wl);
    cudaGetSymbolAddress((void**)&WTh, g_WTh); cudaGetSymbolAddress((void**)&WTl, g_WTl);
    cudaGetSymbolAddress((void**)&Pb[0][0], g_P0h);  cudaGetSymbolAddress((void**)&Pb[0][1], g_P0l);
    cudaGetSymbolAddress((void**)&Pb[0][2], g_P0Th); cudaGetSymbolAddress((void**)&Pb[0][3], g_P0Tl);
    cudaGetSymbolAddress((void**)&Pb[1][0], g_P1h);  cudaGetSymbolAddress((void**)&Pb[1][1], g_P1l);
    cudaGetSymbolAddress((void**)&Pb[1][2], g_P1Th); cudaGetSymbolAddress((void**)&Pb[1][3], g_P1Tl);
    cudaGetSymbolAddress((void**)&X0, g_X0);   cudaGetSymbolAddress((void**)&X1, g_X1);

    cudaFuncSetAttribute(gemm_solo<0>, cudaFuncAttributeMaxDynamicSharedMemorySize, GEMM_SMEM);
    cudaFuncSetAttribute((const void*)gemm_dual<0,1>, cudaFuncAttributeMaxDynamicSharedMemorySize, GEMM_SMEM);

    __half* st[2] = {X0, X1};

    cudaMemsetAsync(psync, 0, sizeof(int) * 8, 0);
    cudaMemcpyAsync(out_h, h0, sizeof(float) * B_DIM * D_DIM, cudaMemcpyDeviceToDevice, 0);

    powiter_kernel<<<128, 256>>>(W, u);
    dim3 trg(32, 32), trb(32, 8);
    split_tr_kernel<<<trg, trb>>>(W, Wh, Wl, WTh, WTl);
    prep1_kernel<<<4096, 256>>>(x, h0, X0);

    dim3 gg(D_DIM / NT, D_DIM / MT);        // (8, 16)
    dim3 gg2(D_DIM / NT, D_DIM / MT, 2);

    // Job builders -------------------------------------------------------------
    auto mkPhase1 = [&](int j) {
        Job J = {};
        J.Ah = st[j & 1]; J.Bh = Wh; J.Bl = Wl;
        J.out = out_h; J.bias = bv;
        J.xnext = (j < 7) ? x : nullptr;
        J.sh = st[(j + 1) & 1];
        J.fdst = (j == 7) ? S0 : nullptr;
        J.emode = 1; J.jstep = j;
        return J;
    };
    // squaring i (1..9): src = W for i==1 else buf[i&1]; dst = buf[(i+1)&1]
    auto mkSq = [&](int i) {
        Job J = {};
        if (i == 1) { J.Ah = Wh; J.Al = Wl; J.Bh = WTh; J.Bl = WTl; }
        else {
            __half** s = Pb[i & 1];
            J.Ah = s[0]; J.Al = s[1]; J.Bh = s[2]; J.Bl = s[3];
        }
        __half** d = Pb[(i + 1) & 1];
        J.ph = d[0]; J.pl = d[1]; J.pth = d[2]; J.ptl = d[3];
        J.emode = 3;
        return J;
    };
    auto mkScan = [&](int r, float* Sc, float* Sn) {
        Job J = {};
        int pbuf = (4 + r) & 1;                 // power buffer for A^{8*2^r}
        J.Ah = st[r & 1]; J.Bh = Pb[pbuf][0]; J.Bl = Pb[pbuf][1];
        J.out = Sn; J.addsrc = Sc;
        J.sh = st[(r + 1) & 1];
        J.ashift = -(1 << r) * B_DIM;
        J.emode = 0;
        return J;
    };
    auto mkPhase3 = [&](int j) {
        Job J = {};
        J.Ah = st[(j + 1) & 1]; J.Bh = Wh; J.Bl = Wl;
        J.out = out_h; J.fdst = out_silu;
        J.sh = (j < 7) ? st[j & 1] : nullptr;
        J.ashift = (j == 0) ? -B_DIM : 0;
        J.emode = 2; J.jstep = j;
        return J;
    };

    // phase1 j0..2 fused with squarings 1..3 (A^2, A^4, A^8)
    for (int j = 0; j < 3; j++)
        gemm_dual<0,1><<<gg2, 256, GEMM_SMEM>>>(mkPhase1(j), mkSq(j + 1));
    // phase1 j3..7 solo
    for (int j = 3; j < 8; j++)
        gemm_solo<0><<<gg, 256, GEMM_SMEM>>>(mkPhase1(j));

    // boundary scan: rounds 0..5 fused with squarings 4..9; round 6 solo
    float* Sc = S0;
    float* Sn = S1;
    for (int r = 0; r < 6; r++) {
        gemm_dual<0,1><<<gg2, 256, GEMM_SMEM>>>(mkScan(r, Sc, Sn), mkSq(r + 4));
        float* tmp = Sc; Sc = Sn; Sn = tmp;
    }
    gemm_solo<0><<<gg, 256, GEMM_SMEM>>>(mkScan(6, Sc, Sn));

    // phase3: fixup + fused silu
    for (int j = 0; j < 8; j++)
        gemm_solo<0><<<gg, 256, GEMM_SMEM>>>(mkPhase3(j));
}

// round 16
// speedup vs baseline: 1.5144x; 1.5144x over previous
#include <cuda_runtime.h>
#include <cuda_fp16.h>
#include <cstdint>
#include <stdint.h>
#include <math.h>

#define D_DIM 1024
#define B_DIM 8
#define T_DIM 1024
#define L_CH 8
#define DD (1024*1024)
#define SPECTRAL_RADIUS 0.999f
#define EPS_F 1e-8f

#define MT 64
#define NT 128
#define KC 32
#define RB 80
#define A_BYTES (MT * RB)
#define B_BYTES (NT * RB)
#define STAGE_BYTES (2 * A_BYTES + 2 * B_BYTES)
#define NSTAGE 4
#define GEMM_SMEM (NSTAGE * STAGE_BYTES)

// ------------------------- device scratch ------------------------------------
__device__ float g_p[6][D_DIM];
__device__ float g_scale;
__device__ int   g_psync[8];
__device__ __align__(256) __half g_Wh[DD], g_Wl[DD], g_WTh[DD], g_WTl[DD];
__device__ __align__(256) __half g_P0h[DD], g_P0l[DD], g_P0Th[DD], g_P0Tl[DD];
__device__ __align__(256) __half g_P1h[DD], g_P1l[DD], g_P1Th[DD], g_P1Tl[DD];
__device__ __align__(256) __half g_X0[DD], g_X1[DD];
__device__ __align__(256) float g_S[2][DD];

// ------------------------- PTX helpers ---------------------------------------
__device__ __forceinline__ unsigned smem_u32(const void* p) {
    unsigned a;
    asm("{ .reg .u64 t; cvta.to.shared.u64 t, %1; cvt.u32.u64 %0, t; }" : "=r"(a) : "l"(p));
    return a;
}
__device__ __forceinline__ void cp16(unsigned sa, const void* g) {
    asm volatile("cp.async.cg.shared.global [%0], [%1], 16;" :: "r"(sa), "l"(g));
}
__device__ __forceinline__ void cp16z(unsigned sa, const void* g, int srcsize) {
    asm volatile("cp.async.cg.shared.global [%0], [%1], 16, %2;"
                 :: "r"(sa), "l"(g), "r"(srcsize));
}
__device__ __forceinline__ void cp_commit() { asm volatile("cp.async.commit_group;"); }
__device__ __forceinline__ void cp_wait0()  { asm volatile("cp.async.wait_group 0;" ::: "memory"); }
__device__ __forceinline__ void cp_wait1()  { asm volatile("cp.async.wait_group 1;" ::: "memory"); }
__device__ __forceinline__ void cp_wait2()  { asm volatile("cp.async.wait_group 2;" ::: "memory"); }

__device__ __forceinline__ void ldsm4(unsigned addr, unsigned* r) {
    asm volatile("ldmatrix.sync.aligned.m8n8.x4.shared.b16 {%0,%1,%2,%3}, [%4];"
                 : "=r"(r[0]), "=r"(r[1]), "=r"(r[2]), "=r"(r[3]) : "r"(addr));
}
__device__ __forceinline__ void mma16816(float* c, const unsigned* a,
                                         unsigned b0, unsigned b1) {
    asm volatile(
        "mma.sync.aligned.m16n8k16.row.col.f32.f16.f16.f32 "
        "{%0,%1,%2,%3}, {%4,%5,%6,%7}, {%8,%9}, {%0,%1,%2,%3};"
        : "+f"(c[0]), "+f"(c[1]), "+f"(c[2]), "+f"(c[3])
        : "r"(a[0]), "r"(a[1]), "r"(a[2]), "r"(a[3]), "r"(b0), "r"(b1));
}

// ------------------------- fused power iteration ------------------------------
__global__ void __launch_bounds__(256, 1)
powiter_kernel(const float* __restrict__ W, const float* __restrict__ u) {
    int tid = threadIdx.x, wid = tid >> 5, lane = tid & 31;
    int outIdx = blockIdx.x * 8 + wid;

    for (int p = 0; p < 6; p++) {
        const float* vin = (p == 0) ? u : g_p[p - 1];
        float acc = 0.f;
        if ((p & 1) == 0) {            // W^T * vin
            for (int e = lane; e < D_DIM; e += 32)
                acc += W[(size_t)e * D_DIM + outIdx] * vin[e];
        } else {                        // W * vin
            const float* row = W + (size_t)outIdx * D_DIM;
            for (int d = lane; d < D_DIM; d += 32)
                acc += row[d] * vin[d];
        }
        #pragma unroll
        for (int o = 16; o; o >>= 1) acc += __shfl_down_sync(0xffffffffu, acc, o);
        if (lane == 0) g_p[p][outIdx] = acc;
        __syncthreads();
        if (tid == 0) {
            __threadfence();
            atomicAdd(&g_psync[p], 1);
            while (*(volatile int*)&g_psync[p] < 128) { }
            __threadfence();
        }
        __syncthreads();
    }

    if (blockIdx.x == 0) {
        __shared__ float red[256];
        __shared__ float ssq[6];
        for (int v = 0; v < 6; v++) {
            float local = 0.f;
            for (int i = tid; i < D_DIM; i += 256) { float x = g_p[v][i]; local += x * x; }
            red[tid] = local;
            __syncthreads();
            for (int s = 128; s; s >>= 1) { if (tid < s) red[tid] += red[tid + s]; __syncthreads(); }
            if (tid == 0) ssq[v] = red[0];
            __syncthreads();
        }
        if (tid == 0) {
            float a1 = 1.f / (sqrtf(ssq[0]) + EPS_F);
            float b1 = a1 / (a1 * sqrtf(ssq[1]) + EPS_F);
            float a2 = b1 / (b1 * sqrtf(ssq[2]) + EPS_F);
            float b2 = a2 / (a2 * sqrtf(ssq[3]) + EPS_F);
            float a3 = b2 / (b2 * sqrtf(ssq[4]) + EPS_F);
            float b3 = a3 / (a3 * sqrtf(ssq[5]) + EPS_F);
            float sigma = fabsf(a3 * b3 * ssq[5]);
            g_scale = SPECTRAL_RADIUS / (sigma + EPS_F);
        }
    }
}

// --------------------- W split (+ transpose), scaled ---------------------------
__global__ void split_tr_kernel(const float* __restrict__ in,
                                __half* __restrict__ oh, __half* __restrict__ ol,
                                __half* __restrict__ oth, __half* __restrict__ otl) {
    __shared__ float tile[32][33];
    float s = g_scale;
    int bx = blockIdx.x, by = blockIdx.y;
    int tx = threadIdx.x, ty = threadIdx.y;     // 32 x 8
    #pragma unroll
    for (int k = 0; k < 4; k++) {
        int r = by * 32 + ty + k * 8, c = bx * 32 + tx;
        float v = in[(size_t)r * D_DIM + c] * s;
        tile[ty + k * 8][tx] = v;
        __half h = __float2half(v);
        oh[(size_t)r * D_DIM + c] = h;
        ol[(size_t)r * D_DIM + c] = __float2half(v - __half2float(h));
    }
    __syncthreads();
    #pragma unroll
    for (int k = 0; k < 4; k++) {
        int rt = bx * 32 + ty + k * 8, ct = by * 32 + tx;
        float v = tile[tx][ty + k * 8];
        __half h = __float2half(v);
        oth[(size_t)rt * D_DIM + ct] = h;
        otl[(size_t)rt * D_DIM + ct] = __float2half(v - __half2float(h));
    }
}

// ------------------------- prep for phase-1 j=0 -------------------------------
__global__ void prep1_kernel(const float* __restrict__ x, const float* __restrict__ h0,
                             __half* __restrict__ a) {
    size_t gid = (size_t)blockIdx.x * 256 + threadIdx.x;
    int m = (int)(gid >> 10), d = (int)(gid & 1023);
    int c = m >> 3, b = m & 7;
    int t = c * L_CH;
    float v = x[((size_t)t * B_DIM + b) * D_DIM + d];
    if (c == 0) v += h0[(size_t)b * D_DIM + d];
    a[gid] = __float2half(v);
}

// ------------------------- job descriptor -------------------------------------
struct Job {
    const __half* Ah; const __half* Al;
    const __half* Bh; const __half* Bl;
    float* out; const float* addsrc; const float* bias; const float* xnext;
    __half* sh; float* fdst;
    __half* ph; __half* pl; __half* pth; __half* ptl;
    int ashift; int jstep;
};
// EMODE (template):
// 0: out = R (+addsrc); optional sh = half(R); copy fast-path for fully-shifted tiles.
// 1: phase1: v+=bias; out_h[slot]=v; sh=half(v + xnext[slot]) (or half(v)); fdst opt.
// 2: phase3: out_h[slot]+=v; silu -> fdst; optional sh=half(v).
// 3: squaring: ph/pl direct; pth/ptl via smem transpose.

template<int HASAL>
__device__ __forceinline__ void load_chunk(unsigned smb, int stage, const Job& J,
                                           int arow0, int col0, int kc, int tid) {
    unsigned sb = smb + stage * STAGE_BYTES;
    #pragma unroll
    for (int i = 0; i < (HASAL ? 2 : 1); i++) {
        int e = tid + i * 256;
        int arr = e >> 8;
        int rr = (e & 255) >> 2;
        int cc = e & 3;
        const __half* src = arr ? J.Al : J.Ah;
        int r = arow0 + rr + J.ashift;
        int sz = (r >= 0) ? 16 : 0;
        if (r < 0) r = 0;
        cp16z(sb + arr * A_BYTES + rr * RB + cc * 16,
              src + (size_t)r * D_DIM + kc * KC + cc * 8, sz);
    }
    #pragma unroll
    for (int i = 0; i < 4; i++) {
        int e = tid + i * 256;
        int arr = e >> 9;
        int rr = (e & 511) >> 2;
        int cc = e & 3;
        const __half* src = arr ? J.Bl : J.Bh;
        cp16(sb + 2 * A_BYTES + arr * B_BYTES + rr * RB + cc * 16,
             src + (size_t)(col0 + rr) * D_DIM + kc * KC + cc * 8);
    }
    cp_commit();
}

template<int HASAL, int EMODE>
__global__ void __launch_bounds__(256, 1) gemm_kernel(const Job J) {
    extern __shared__ char sm[];
    unsigned smb = smem_u32(sm);
    const int tid = threadIdx.x;
    const int wid = tid >> 5, lane = tid & 31;
    const int bx = blockIdx.x, by = blockIdx.y;
    const int warp_m = wid >> 2, warp_n = wid & 3;
    const int g = lane >> 2, tg = lane & 3;

    const int arow0 = by * MT, col0 = bx * NT;

    if (EMODE == 0 && J.ashift != 0 && arow0 + MT <= -J.ashift) {
        #pragma unroll 4
        for (int i = 0; i < 16; i++) {
            int e = tid + i * 256;
            int r = e >> 6, c2 = e & 63;
            size_t flat = (size_t)(arow0 + r) * D_DIM + col0 + c2 * 2;
            float2 v = *(const float2*)(J.addsrc + flat);
            *(float2*)(J.out + flat) = v;
            if (J.sh) *(__half2*)(J.sh + flat) = __floats2half2_rn(v.x, v.y);
        }
        return;
    }

    unsigned lrow = lane & 15, lhalf = lane >> 4;
    unsigned aBase = smb + (warp_m * 32 + lrow) * RB + lhalf * 16;
    unsigned bBase = smb + 2 * A_BYTES + (warp_n * 32 + lrow) * RB + lhalf * 16;

    float acc[2][4][4];
    #pragma unroll
    for (int i = 0; i < 2; i++)
        #pragma unroll
        for (int j = 0; j < 4; j++)
            #pragma unroll
            for (int q = 0; q < 4; q++) acc[i][j][q] = 0.f;

    const int NKC = D_DIM / KC;   // 32
    #pragma unroll
    for (int s = 0; s < NSTAGE - 1; s++)
        load_chunk<HASAL>(smb, s, J, arow0, col0, s, tid);

    for (int kc = 0; kc < NKC; kc++) {
        int st = kc & (NSTAGE - 1);
        int remain = NKC - 1 - kc;
        if (remain >= 2) cp_wait2();
        else if (remain == 1) cp_wait1();
        else cp_wait0();
        __syncthreads();
        if (kc + NSTAGE - 1 < NKC)
            load_chunk<HASAL>(smb, (kc + NSTAGE - 1) & (NSTAGE - 1),
                              J, arow0, col0, kc + NSTAGE - 1, tid);

        unsigned sa = aBase + st * STAGE_BYTES;
        unsigned sb = bBase + st * STAGE_BYTES;
        #pragma unroll
        for (int ks = 0; ks < 2; ks++) {
            unsigned ko = ks * 32;
            unsigned AH0[4], AH1[4];
            ldsm4(sa + ko, AH0);
            ldsm4(sa + 16 * RB + ko, AH1);
            unsigned AL0[4], AL1[4];
            if (HASAL) {
                ldsm4(sa + A_BYTES + ko, AL0);
                ldsm4(sa + A_BYTES + 16 * RB + ko, AL1);
            }
            unsigned BH0[4], BH1[4], BL0[4], BL1[4];
            ldsm4(sb + ko, BH0);
            ldsm4(sb + 16 * RB + ko, BH1);
            ldsm4(sb + B_BYTES + ko, BL0);
            ldsm4(sb + B_BYTES + 16 * RB + ko, BL1);

            unsigned bh[4][2] = {{BH0[0],BH0[2]},{BH0[1],BH0[3]},
                                 {BH1[0],BH1[2]},{BH1[1],BH1[3]}};
            unsigned bl[4][2] = {{BL0[0],BL0[2]},{BL0[1],BL0[3]},
                                 {BL1[0],BL1[2]},{BL1[1],BL1[3]}};
            #pragma unroll
            for (int j = 0; j < 4; j++) {
                mma16816(acc[0][j], AH0, bh[j][0], bh[j][1]);
                mma16816(acc[0][j], AH0, bl[j][0], bl[j][1]);
                if (HASAL) mma16816(acc[0][j], AL0, bh[j][0], bh[j][1]);
                mma16816(acc[1][j], AH1, bh[j][0], bh[j][1]);
                mma16816(acc[1][j], AH1, bl[j][0], bl[j][1]);
                if (HASAL) mma16816(acc[1][j], AL1, bh[j][0], bh[j][1]);
            }
        }
    }

    if (EMODE == 3) {
        __syncthreads();
        float* ts = (float*)sm;                 // [128 cols][66 rows]
        #pragma unroll
        for (int i = 0; i < 2; i++) {
            #pragma unroll
            for (int j = 0; j < 4; j++) {
                int rl_base = warp_m * 32 + i * 16 + g;
                int cl = warp_n * 32 + j * 8 + tg * 2;
                #pragma unroll
                for (int half = 0; half < 2; half++) {
                    int rl = rl_base + half * 8;
                    float vx = acc[i][j][half * 2 + 0];
                    float vy = acc[i][j][half * 2 + 1];
                    size_t flat = (size_t)(arow0 + rl) * D_DIM + col0 + cl;
                    __half hx = __float2half(vx);
                    __half hy = __float2half(vy);
                    __half2 h2; h2.x = hx; h2.y = hy;
                    __half2 l2;
                    l2.x = __float2half(vx - __half2float(hx));
                    l2.y = __float2half(vy - __half2float(hy));
                    *(__half2*)(J.ph + flat) = h2;
                    *(__half2*)(J.pl + flat) = l2;
                    ts[cl * 66 + rl] = vx;
                    ts[(cl + 1) * 66 + rl] = vy;
                }
            }
        }
        __syncthreads();
        #pragma unroll
        for (int c16 = 0; c16 < 16; c16++) {
            int cl = wid * 16 + c16;
            float v0 = ts[cl * 66 + 2 * lane];
            float v1 = ts[cl * 66 + 2 * lane + 1];
            __half h0 = __float2half(v0), h1 = __float2half(v1);
            __half2 h2; h2.x = h0; h2.y = h1;
            __half2 l2;
            l2.x = __float2half(v0 - __half2float(h0));
            l2.y = __float2half(v1 - __half2float(h1));
            size_t off = (size_t)(col0 + cl) * D_DIM + arow0 + 2 * lane;
            *(__half2*)(J.pth + off) = h2;
            *(__half2*)(J.ptl + off) = l2;
        }
        return;
    }

    #pragma unroll
    for (int i = 0; i < 2; i++) {
        #pragma unroll
        for (int j = 0; j < 4; j++) {
            int rm = arow0 + warp_m * 32 + i * 16 + g;
            int col = col0 + warp_n * 32 + j * 8 + tg * 2;
            #pragma unroll
            for (int half = 0; half < 2; half++) {
                int r = rm + half * 8;
                float vx = acc[i][j][half * 2 + 0];
                float vy = acc[i][j][half * 2 + 1];
                size_t flat = (size_t)r * D_DIM + col;
                if (EMODE == 0) {
                    if (J.addsrc) {
                        float2 a2 = *(const float2*)(J.addsrc + flat);
                        vx += a2.x; vy += a2.y;
                    }
                    float2 o; o.x = vx; o.y = vy;
                    *(float2*)(J.out + flat) = o;
                    if (J.sh)
                        *(__half2*)(J.sh + flat) = __floats2half2_rn(vx, vy);
                } else {
                    int c = r >> 3, b = r & 7;
                    int t1 = c * L_CH + J.jstep + 1;
                    size_t idx = ((size_t)t1 * B_DIM + b) * D_DIM + col;
                    if (EMODE == 1) {
                        float2 b2 = *(const float2*)(J.bias + col);
                        vx += b2.x; vy += b2.y;
                        float2 o; o.x = vx; o.y = vy;
                        *(float2*)(J.out + idx) = o;
                        if (J.fdst) { float2 f; f.x = vx; f.y = vy;
                                      *(float2*)(J.fdst + flat) = f; }
                        float sx = vx, sy = vy;
                        if (J.xnext) {
                            float2 xv = *(const float2*)(J.xnext + idx);
                            sx += xv.x; sy += xv.y;
                        }
                        *(__half2*)(J.sh + flat) = __floats2half2_rn(sx, sy);
                    } else {  // EMODE == 2
                        float2 o = *(const float2*)(J.out + idx);
                        o.x += vx; o.y += vy;
                        *(float2*)(J.out + idx) = o;
                        float2 sv;
                        sv.x = o.x / (1.f + expf(-o.x));
                        sv.y = o.y / (1.f + expf(-o.y));
                        *(float2*)(J.fdst + idx - (size_t)B_DIM * D_DIM) = sv;
                        if (J.sh)
                            *(__half2*)(J.sh + flat) = __floats2half2_rn(vx, vy);
                    }
                }
            }
        }
    }
}

// ------------------------------- launcher ------------------------------------
extern "C" void kernel_launch(void* const* d_in, const int* in_sizes, int n_in,
                              void* d_out, int out_size) {
    const float* x  = (const float*)d_in[0];
    const float* h0 = (const float*)d_in[1];
    const float* W  = (const float*)d_in[2];
    const float* bv = (const float*)d_in[3];
    const float* u  = (const float*)d_in[4];

    float* out_silu = (float*)d_out;
    float* out_h    = (float*)d_out + (size_t)T_DIM * B_DIM * D_DIM;  // h[0..T]

    float *S0, *S1; void* psync;
    __half *Wh, *Wl, *WTh, *WTl, *X0, *X1;
    __half *Pb[2][4];
    cudaGetSymbolAddress((void**)&S0, g_S);   S1 = S0 + DD;
    cudaGetSymbolAddress(&psync, g_psync);
    cudaGetSymbolAddress((void**)&Wh, g_Wh);   cudaGetSymbolAddress((void**)&Wl, g_Wl);
    cudaGetSymbolAddress((void**)&WTh, g_WTh); cudaGetSymbolAddress((void**)&WTl, g_WTl);
    cudaGetSymbolAddress((void**)&Pb[0][0], g_P0h);  cudaGetSymbolAddress((void**)&Pb[0][1], g_P0l);
    cudaGetSymbolAddress((void**)&Pb[0][2], g_P0Th); cudaGetSymbolAddress((void**)&Pb[0][3], g_P0Tl);
    cudaGetSymbolAddress((void**)&Pb[1][0], g_P1h);  cudaGetSymbolAddress((void**)&Pb[1][1], g_P1l);
    cudaGetSymbolAddress((void**)&Pb[1][2], g_P1Th); cudaGetSymbolAddress((void**)&Pb[1][3], g_P1Tl);
    cudaGetSymbolAddress((void**)&X0, g_X0);   cudaGetSymbolAddress((void**)&X1, g_X1);

    cudaFuncSetAttribute(gemm_kernel<0,0>, cudaFuncAttributeMaxDynamicSharedMemorySize, GEMM_SMEM);
    cudaFuncSetAttribute(gemm_kernel<0,1>, cudaFuncAttributeMaxDynamicSharedMemorySize, GEMM_SMEM);
    cudaFuncSetAttribute(gemm_kernel<0,2>, cudaFuncAttributeMaxDynamicSharedMemorySize, GEMM_SMEM);
    cudaFuncSetAttribute(gemm_kernel<1,3>, cudaFuncAttributeMaxDynamicSharedMemorySize, GEMM_SMEM);

    __half* st[2] = {X0, X1};

    cudaMemsetAsync(psync, 0, sizeof(int) * 8, 0);
    cudaMemcpyAsync(out_h, h0, sizeof(float) * B_DIM * D_DIM, cudaMemcpyDeviceToDevice, 0);

    powiter_kernel<<<128, 256>>>(W, u);
    dim3 trg(32, 32), trb(32, 8);
    split_tr_kernel<<<trg, trb>>>(W, Wh, Wl, WTh, WTl);
    prep1_kernel<<<4096, 256>>>(x, h0, X0);

    dim3 gg(D_DIM / NT, D_DIM / MT);        // (8, 16)

    auto mkPhase1 = [&](int j) {
        Job J = {};
        J.Ah = st[j & 1]; J.Bh = Wh; J.Bl = Wl;
        J.out = out_h; J.bias = bv;
        J.xnext = (j < 7) ? x : nullptr;
        J.sh = st[(j + 1) & 1];
        J.fdst = (j == 7) ? S0 : nullptr;
        J.jstep = j;
        return J;
    };
    auto mkSq = [&](int i) {   // squaring i (1..9): A^(2^(i-1)) -> A^(2^i)
        Job J = {};
        if (i == 1) { J.Ah = Wh; J.Al = Wl; J.Bh = WTh; J.Bl = WTl; }
        else {
            __half** s = Pb[i & 1];
            J.Ah = s[0]; J.Al = s[1]; J.Bh = s[2]; J.Bl = s[3];
        }
        __half** d = Pb[(i + 1) & 1];
        J.ph = d[0]; J.pl = d[1]; J.pth = d[2]; J.ptl = d[3];
        return J;
    };
    auto mkScan = [&](int r, float* Sc, float* Sn) {
        Job J = {};
        int pbuf = (4 + r) & 1;                 // A^(2^(3+r)) buffer
        J.Ah = st[r & 1]; J.Bh = Pb[pbuf][0]; J.Bl = Pb[pbuf][1];
        J.out = Sn; J.addsrc = Sc;
        J.sh = st[(r + 1) & 1];
        J.ashift = -(1 << r) * B_DIM;
        return J;
    };
    auto mkPhase3 = [&](int j) {
        Job J = {};
        J.Ah = st[(j + 1) & 1]; J.Bh = Wh; J.Bl = Wl;
        J.out = out_h; J.fdst = out_silu;
        J.sh = (j < 7) ? st[j & 1] : nullptr;
        J.ashift = (j == 0) ? -B_DIM : 0;
        J.jstep = j;
        return J;
    };

    // phase 1 (8 GEMMs, 2-product)
    for (int j = 0; j < 8; j++)
        gemm_kernel<0,1><<<gg, 256, GEMM_SMEM>>>(mkPhase1(j));

    // squarings A^2, A^4, A^8 (3-product, fused split+transpose epilogue)
    for (int i = 1; i <= 3; i++)
        gemm_kernel<1,3><<<gg, 256, GEMM_SMEM>>>(mkSq(i));

    // boundary scan interleaved with remaining squarings
    float* Sc = S0;
    float* Sn = S1;
    for (int r = 0; r < 7; r++) {
        gemm_kernel<0,0><<<gg, 256, GEMM_SMEM>>>(mkScan(r, Sc, Sn));
        float* tmp = Sc; Sc = Sn; Sn = tmp;
        if (r < 6)
            gemm_kernel<1,3><<<gg, 256, GEMM_SMEM>>>(mkSq(r + 4));
    }

    // phase 3: fixup + fused silu
    for (int j = 0; j < 8; j++)
        gemm_kernel<0,2><<<gg, 256, GEMM_SMEM>>>(mkPhase3(j));
}

// round 17
// speedup vs baseline: 1.5966x; 1.0543x over previous
#include <cuda_runtime.h>
#include <cuda_fp16.h>
#include <cstdint>
#include <stdint.h>
#include <math.h>

#define D_DIM 1024
#define B_DIM 8
#define T_DIM 1024
#define L_CH 8
#define DD (1024*1024)
#define SPECTRAL_RADIUS 0.999f
#define EPS_F 1e-8f

#define MT 64
#define NT 128
#define KC 32
#define RB 80
#define A_BYTES (MT * RB)
#define B_BYTES (NT * RB)
#define STAGE_BYTES (2 * A_BYTES + 2 * B_BYTES)
#define NSTAGE 4
#define GEMM_SMEM (NSTAGE * STAGE_BYTES)
#define NTHR 512

// ------------------------- device scratch ------------------------------------
__device__ float g_p[6][D_DIM];
__device__ float g_scale;
__device__ int   g_psync[8];
__device__ __align__(256) __half g_Wh[DD], g_Wl[DD], g_WTh[DD], g_WTl[DD];
__device__ __align__(256) __half g_P0h[DD], g_P0l[DD], g_P0Th[DD], g_P0Tl[DD];
__device__ __align__(256) __half g_P1h[DD], g_P1l[DD], g_P1Th[DD], g_P1Tl[DD];
__device__ __align__(256) __half g_X0[DD], g_X1[DD];
__device__ __align__(256) float g_S[2][DD];

// ------------------------- PTX helpers ---------------------------------------
__device__ __forceinline__ unsigned smem_u32(const void* p) {
    unsigned a;
    asm("{ .reg .u64 t; cvta.to.shared.u64 t, %1; cvt.u32.u64 %0, t; }" : "=r"(a) : "l"(p));
    return a;
}
__device__ __forceinline__ void cp16(unsigned sa, const void* g) {
    asm volatile("cp.async.cg.shared.global [%0], [%1], 16;" :: "r"(sa), "l"(g));
}
__device__ __forceinline__ void cp16z(unsigned sa, const void* g, int srcsize) {
    asm volatile("cp.async.cg.shared.global [%0], [%1], 16, %2;"
                 :: "r"(sa), "l"(g), "r"(srcsize));
}
__device__ __forceinline__ void cp_commit() { asm volatile("cp.async.commit_group;"); }
__device__ __forceinline__ void cp_wait0()  { asm volatile("cp.async.wait_group 0;" ::: "memory"); }
__device__ __forceinline__ void cp_wait1()  { asm volatile("cp.async.wait_group 1;" ::: "memory"); }
__device__ __forceinline__ void cp_wait2()  { asm volatile("cp.async.wait_group 2;" ::: "memory"); }

__device__ __forceinline__ void ldsm4(unsigned addr, unsigned* r) {
    asm volatile("ldmatrix.sync.aligned.m8n8.x4.shared.b16 {%0,%1,%2,%3}, [%4];"
                 : "=r"(r[0]), "=r"(r[1]), "=r"(r[2]), "=r"(r[3]) : "r"(addr));
}
__device__ __forceinline__ void mma16816(float* c, const unsigned* a,
                                         unsigned b0, unsigned b1) {
    asm volatile(
        "mma.sync.aligned.m16n8k16.row.col.f32.f16.f16.f32 "
        "{%0,%1,%2,%3}, {%4,%5,%6,%7}, {%8,%9}, {%0,%1,%2,%3};"
        : "+f"(c[0]), "+f"(c[1]), "+f"(c[2]), "+f"(c[3])
        : "r"(a[0]), "r"(a[1]), "r"(a[2]), "r"(a[3]), "r"(b0), "r"(b1));
}

// ------------------------- fused power iteration ------------------------------
__global__ void __launch_bounds__(256, 1)
powiter_kernel(const float* __restrict__ W, const float* __restrict__ u) {
    int tid = threadIdx.x, wid = tid >> 5, lane = tid & 31;
    int outIdx = blockIdx.x * 8 + wid;

    for (int p = 0; p < 6; p++) {
        const float* vin = (p == 0) ? u : g_p[p - 1];
        float acc = 0.f;
        if ((p & 1) == 0) {
            for (int e = lane; e < D_DIM; e += 32)
                acc += W[(size_t)e * D_DIM + outIdx] * vin[e];
        } else {
            const float* row = W + (size_t)outIdx * D_DIM;
            for (int d = lane; d < D_DIM; d += 32)
                acc += row[d] * vin[d];
        }
        #pragma unroll
        for (int o = 16; o; o >>= 1) acc += __shfl_down_sync(0xffffffffu, acc, o);
        if (lane == 0) g_p[p][outIdx] = acc;
        __syncthreads();
        if (tid == 0) {
            __threadfence();
            atomicAdd(&g_psync[p], 1);
            while (*(volatile int*)&g_psync[p] < 128) { }
            __threadfence();
        }
        __syncthreads();
    }

    if (blockIdx.x == 0) {
        __shared__ float red[256];
        __shared__ float ssq[6];
        for (int v = 0; v < 6; v++) {
            float local = 0.f;
            for (int i = tid; i < D_DIM; i += 256) { float x = g_p[v][i]; local += x * x; }
            red[tid] = local;
            __syncthreads();
            for (int s = 128; s; s >>= 1) { if (tid < s) red[tid] += red[tid + s]; __syncthreads(); }
            if (tid == 0) ssq[v] = red[0];
            __syncthreads();
        }
        if (tid == 0) {
            float a1 = 1.f / (sqrtf(ssq[0]) + EPS_F);
            float b1 = a1 / (a1 * sqrtf(ssq[1]) + EPS_F);
            float a2 = b1 / (b1 * sqrtf(ssq[2]) + EPS_F);
            float b2 = a2 / (a2 * sqrtf(ssq[3]) + EPS_F);
            float a3 = b2 / (b2 * sqrtf(ssq[4]) + EPS_F);
            float b3 = a3 / (a3 * sqrtf(ssq[5]) + EPS_F);
            float sigma = fabsf(a3 * b3 * ssq[5]);
            g_scale = SPECTRAL_RADIUS / (sigma + EPS_F);
        }
    }
}

// --------------------- W split (+ transpose), scaled ---------------------------
__global__ void split_tr_kernel(const float* __restrict__ in,
                                __half* __restrict__ oh, __half* __restrict__ ol,
                                __half* __restrict__ oth, __half* __restrict__ otl) {
    __shared__ float tile[32][33];
    float s = g_scale;
    int bx = blockIdx.x, by = blockIdx.y;
    int tx = threadIdx.x, ty = threadIdx.y;     // 32 x 8
    #pragma unroll
    for (int k = 0; k < 4; k++) {
        int r = by * 32 + ty + k * 8, c = bx * 32 + tx;
        float v = in[(size_t)r * D_DIM + c] * s;
        tile[ty + k * 8][tx] = v;
        __half h = __float2half(v);
        oh[(size_t)r * D_DIM + c] = h;
        ol[(size_t)r * D_DIM + c] = __float2half(v - __half2float(h));
    }
    __syncthreads();
    #pragma unroll
    for (int k = 0; k < 4; k++) {
        int rt = bx * 32 + ty + k * 8, ct = by * 32 + tx;
        float v = tile[tx][ty + k * 8];
        __half h = __float2half(v);
        oth[(size_t)rt * D_DIM + ct] = h;
        otl[(size_t)rt * D_DIM + ct] = __float2half(v - __half2float(h));
    }
}

// ------------------------- prep for phase-1 j=0 -------------------------------
__global__ void prep1_kernel(const float* __restrict__ x, const float* __restrict__ h0,
                             __half* __restrict__ a) {
    size_t gid = (size_t)blockIdx.x * 256 + threadIdx.x;
    int m = (int)(gid >> 10), d = (int)(gid & 1023);
    int c = m >> 3, b = m & 7;
    int t = c * L_CH;
    float v = x[((size_t)t * B_DIM + b) * D_DIM + d];
    if (c == 0) v += h0[(size_t)b * D_DIM + d];
    a[gid] = __float2half(v);
}

// ------------------------- job descriptor -------------------------------------
struct Job {
    const __half* Ah; const __half* Al;
    const __half* Bh; const __half* Bl;
    float* out; const float* addsrc; const float* bias; const float* xnext;
    __half* sh; float* fdst;
    __half* ph; __half* pl; __half* pth; __half* ptl;
    int ashift; int jstep;
};

template<int HASAL>
__device__ __forceinline__ void load_chunk(unsigned smb, int stage, const Job& J,
                                           int arow0, int col0, int kc, int tid) {
    unsigned sb = smb + stage * STAGE_BYTES;
    if (HASAL) {                    // 512 A entries (Ah, Al)
        int arr = tid >> 8;
        int rr = (tid & 255) >> 2;
        int cc = tid & 3;
        const __half* src = arr ? J.Al : J.Ah;
        int r = arow0 + rr + J.ashift;
        int sz = (r >= 0) ? 16 : 0;
        if (r < 0) r = 0;
        cp16z(sb + arr * A_BYTES + rr * RB + cc * 16,
              src + (size_t)r * D_DIM + kc * KC + cc * 8, sz);
    } else if (tid < 256) {         // 256 A entries (Ah only)
        int rr = tid >> 2;
        int cc = tid & 3;
        int r = arow0 + rr + J.ashift;
        int sz = (r >= 0) ? 16 : 0;
        if (r < 0) r = 0;
        cp16z(sb + rr * RB + cc * 16,
              J.Ah + (size_t)r * D_DIM + kc * KC + cc * 8, sz);
    }
    #pragma unroll
    for (int i = 0; i < 2; i++) {   // 1024 B entries (Bh, Bl)
        int e = tid + i * NTHR;
        int arr = e >> 9;
        int rr = (e & 511) >> 2;
        int cc = e & 3;
        const __half* src = arr ? J.Bl : J.Bh;
        cp16(sb + 2 * A_BYTES + arr * B_BYTES + rr * RB + cc * 16,
             src + (size_t)(col0 + rr) * D_DIM + kc * KC + cc * 8);
    }
    cp_commit();
}

template<int HASAL, int EMODE>
__global__ void __launch_bounds__(NTHR, 1) gemm_kernel(const Job J) {
    extern __shared__ char sm[];
    unsigned smb = smem_u32(sm);
    const int tid = threadIdx.x;
    const int wid = tid >> 5, lane = tid & 31;
    const int bx = blockIdx.x, by = blockIdx.y;
    const int warp_m = wid >> 3, warp_n = wid & 7;   // 2 x 8 warps
    const int g = lane >> 2, tg = lane & 3;

    const int arow0 = by * MT, col0 = bx * NT;

    if (EMODE == 0 && J.ashift != 0 && arow0 + MT <= -J.ashift) {
        #pragma unroll 4
        for (int i = 0; i < 8; i++) {
            int e = tid + i * NTHR;           // 4096 float2 per tile
            int r = e >> 6, c2 = e & 63;
            size_t flat = (size_t)(arow0 + r) * D_DIM + col0 + c2 * 2;
            float2 v = *(const float2*)(J.addsrc + flat);
            *(float2*)(J.out + flat) = v;
            if (J.sh) *(__half2*)(J.sh + flat) = __floats2half2_rn(v.x, v.y);
        }
        return;
    }

    unsigned lrow = lane & 15, lhalf = lane >> 4;
    unsigned aBase = smb + (warp_m * 32 + lrow) * RB + lhalf * 16;
    unsigned bBase = smb + 2 * A_BYTES + (warp_n * 16 + lrow) * RB + lhalf * 16;

    float acc[2][2][4];
    #pragma unroll
    for (int i = 0; i < 2; i++)
        #pragma unroll
        for (int j = 0; j < 2; j++)
            #pragma unroll
            for (int q = 0; q < 4; q++) acc[i][j][q] = 0.f;

    const int NKC = D_DIM / KC;   // 32
    #pragma unroll
    for (int s = 0; s < NSTAGE - 1; s++)
        load_chunk<HASAL>(smb, s, J, arow0, col0, s, tid);

    for (int kc = 0; kc < NKC; kc++) {
        int st = kc & (NSTAGE - 1);
        int remain = NKC - 1 - kc;
        if (remain >= 2) cp_wait2();
        else if (remain == 1) cp_wait1();
        else cp_wait0();
        __syncthreads();
        if (kc + NSTAGE - 1 < NKC)
            load_chunk<HASAL>(smb, (kc + NSTAGE - 1) & (NSTAGE - 1),
                              J, arow0, col0, kc + NSTAGE - 1, tid);

        unsigned sa = aBase + st * STAGE_BYTES;
        unsigned sb = bBase + st * STAGE_BYTES;
        #pragma unroll
        for (int ks = 0; ks < 2; ks++) {
            unsigned ko = ks * 32;
            unsigned AH0[4], AH1[4];
            ldsm4(sa + ko, AH0);
            ldsm4(sa + 16 * RB + ko, AH1);
            unsigned AL0[4], AL1[4];
            if (HASAL) {
                ldsm4(sa + A_BYTES + ko, AL0);
                ldsm4(sa + A_BYTES + 16 * RB + ko, AL1);
            }
            unsigned BH[4], BL[4];
            ldsm4(sb + ko, BH);              // 16 n-rows x 16 k
            ldsm4(sb + B_BYTES + ko, BL);

            unsigned bh[2][2] = {{BH[0], BH[2]}, {BH[1], BH[3]}};
            unsigned bl[2][2] = {{BL[0], BL[2]}, {BL[1], BL[3]}};
            #pragma unroll
            for (int j = 0; j < 2; j++) {
                mma16816(acc[0][j], AH0, bh[j][0], bh[j][1]);
                mma16816(acc[0][j], AH0, bl[j][0], bl[j][1]);
                if (HASAL) mma16816(acc[0][j], AL0, bh[j][0], bh[j][1]);
                mma16816(acc[1][j], AH1, bh[j][0], bh[j][1]);
                mma16816(acc[1][j], AH1, bl[j][0], bl[j][1]);
                if (HASAL) mma16816(acc[1][j], AL1, bh[j][0], bh[j][1]);
            }
        }
    }

    if (EMODE == 3) {
        __syncthreads();
        float* ts = (float*)sm;                 // [128 cols][66]
        #pragma unroll
        for (int i = 0; i < 2; i++) {
            #pragma unroll
            for (int j = 0; j < 2; j++) {
                int rl_base = warp_m * 32 + i * 16 + g;
                int cl = warp_n * 16 + j * 8 + tg * 2;
                #pragma unroll
                for (int half = 0; half < 2; half++) {
                    int rl = rl_base + half * 8;
                    float vx = acc[i][j][half * 2 + 0];
                    float vy = acc[i][j][half * 2 + 1];
                    size_t flat = (size_t)(arow0 + rl) * D_DIM + col0 + cl;
                    __half hx = __float2half(vx);
                    __half hy = __float2half(vy);
                    __half2 h2; h2.x = hx; h2.y = hy;
                    __half2 l2;
                    l2.x = __float2half(vx - __half2float(hx));
                    l2.y = __float2half(vy - __half2float(hy));
                    *(__half2*)(J.ph + flat) = h2;
                    *(__half2*)(J.pl + flat) = l2;
                    ts[cl * 66 + rl] = vx;
                    ts[(cl + 1) * 66 + rl] = vy;
                }
            }
        }
        __syncthreads();
        #pragma unroll
        for (int c8 = 0; c8 < 8; c8++) {
            int cl = wid * 8 + c8;
            float v0 = ts[cl * 66 + 2 * lane];
            float v1 = ts[cl * 66 + 2 * lane + 1];
            __half h0 = __float2half(v0), h1 = __float2half(v1);
            __half2 h2; h2.x = h0; h2.y = h1;
            __half2 l2;
            l2.x = __float2half(v0 - __half2float(h0));
            l2.y = __float2half(v1 - __half2float(h1));
            size_t off = (size_t)(col0 + cl) * D_DIM + arow0 + 2 * lane;
            *(__half2*)(J.pth + off) = h2;
            *(__half2*)(J.ptl + off) = l2;
        }
        return;
    }

    #pragma unroll
    for (int i = 0; i < 2; i++) {
        #pragma unroll
        for (int j = 0; j < 2; j++) {
            int rm = arow0 + warp_m * 32 + i * 16 + g;
            int col = col0 + warp_n * 16 + j * 8 + tg * 2;
            #pragma unroll
            for (int half = 0; half < 2; half++) {
                int r = rm + half * 8;
                float vx = acc[i][j][half * 2 + 0];
                float vy = acc[i][j][half * 2 + 1];
                size_t flat = (size_t)r * D_DIM + col;
                if (EMODE == 0) {
                    if (J.addsrc) {
                        float2 a2 = *(const float2*)(J.addsrc + flat);
                        vx += a2.x; vy += a2.y;
                    }
                    float2 o; o.x = vx; o.y = vy;
                    *(float2*)(J.out + flat) = o;
                    if (J.sh)
                        *(__half2*)(J.sh + flat) = __floats2half2_rn(vx, vy);
                } else {
                    int c = r >> 3, b = r & 7;
                    int t1 = c * L_CH + J.jstep + 1;
                    size_t idx = ((size_t)t1 * B_DIM + b) * D_DIM + col;
                    if (EMODE == 1) {
                        float2 b2 = *(const float2*)(J.bias + col);
                        vx += b2.x; vy += b2.y;
                        float2 o; o.x = vx; o.y = vy;
                        *(float2*)(J.out + idx) = o;
                        if (J.fdst) { float2 f; f.x = vx; f.y = vy;
                                      *(float2*)(J.fdst + flat) = f; }
                        float sx = vx, sy = vy;
                        if (J.xnext) {
                            float2 xv = *(const float2*)(J.xnext + idx);
                            sx += xv.x; sy += xv.y;
                        }
                        *(__half2*)(J.sh + flat) = __floats2half2_rn(sx, sy);
                    } else {  // EMODE == 2
                        float2 o = *(const float2*)(J.out + idx);
                        o.x += vx; o.y += vy;
                        *(float2*)(J.out + idx) = o;
                        float2 sv;
                        sv.x = o.x / (1.f + expf(-o.x));
                        sv.y = o.y / (1.f + expf(-o.y));
                        *(float2*)(J.fdst + idx - (size_t)B_DIM * D_DIM) = sv;
                        if (J.sh)
                            *(__half2*)(J.sh + flat) = __floats2half2_rn(vx, vy);
                    }
                }
            }
        }
    }
}

// ------------------------------- launcher ------------------------------------
extern "C" void kernel_launch(void* const* d_in, const int* in_sizes, int n_in,
                              void* d_out, int out_size) {
    const float* x  = (const float*)d_in[0];
    const float* h0 = (const float*)d_in[1];
    const float* W  = (const float*)d_in[2];
    const float* bv = (const float*)d_in[3];
    const float* u  = (const float*)d_in[4];

    float* out_silu = (float*)d_out;
    float* out_h    = (float*)d_out + (size_t)T_DIM * B_DIM * D_DIM;  // h[0..T]

    float *S0, *S1; void* psync;
    __half *Wh, *Wl, *WTh, *WTl, *X0, *X1;
    __half *Pb[2][4];
    cudaGetSymbolAddress((void**)&S0, g_S);   S1 = S0 + DD;
    cudaGetSymbolAddress(&psync, g_psync);
    cudaGetSymbolAddress((void**)&Wh, g_Wh);   cudaGetSymbolAddress((void**)&Wl, g_Wl);
    cudaGetSymbolAddress((void**)&WTh, g_WTh); cudaGetSymbolAddress((void**)&WTl, g_WTl);
    cudaGetSymbolAddress((void**)&Pb[0][0], g_P0h);  cudaGetSymbolAddress((void**)&Pb[0][1], g_P0l);
    cudaGetSymbolAddress((void**)&Pb[0][2], g_P0Th); cudaGetSymbolAddress((void**)&Pb[0][3], g_P0Tl);
    cudaGetSymbolAddress((void**)&Pb[1][0], g_P1h);  cudaGetSymbolAddress((void**)&Pb[1][1], g_P1l);
    cudaGetSymbolAddress((void**)&Pb[1][2], g_P1Th); cudaGetSymbolAddress((void**)&Pb[1][3], g_P1Tl);
    cudaGetSymbolAddress((void**)&X0, g_X0);   cudaGetSymbolAddress((void**)&X1, g_X1);

    cudaFuncSetAttribute(gemm_kernel<0,0>, cudaFuncAttributeMaxDynamicSharedMemorySize, GEMM_SMEM);
    cudaFuncSetAttribute(gemm_kernel<0,1>, cudaFuncAttributeMaxDynamicSharedMemorySize, GEMM_SMEM);
    cudaFuncSetAttribute(gemm_kernel<0,2>, cudaFuncAttributeMaxDynamicSharedMemorySize, GEMM_SMEM);
    cudaFuncSetAttribute(gemm_kernel<1,3>, cudaFuncAttributeMaxDynamicSharedMemorySize, GEMM_SMEM);

    __half* st[2] = {X0, X1};

    cudaMemsetAsync(psync, 0, sizeof(int) * 8, 0);
    cudaMemcpyAsync(out_h, h0, sizeof(float) * B_DIM * D_DIM, cudaMemcpyDeviceToDevice, 0);

    powiter_kernel<<<128, 256>>>(W, u);
    dim3 trg(32, 32), trb(32, 8);
    split_tr_kernel<<<trg, trb>>>(W, Wh, Wl, WTh, WTl);
    prep1_kernel<<<4096, 256>>>(x, h0, X0);

    dim3 gg(D_DIM / NT, D_DIM / MT);        // (8, 16)

    auto mkPhase1 = [&](int j) {
        Job J = {};
        J.Ah = st[j & 1]; J.Bh = Wh; J.Bl = Wl;
        J.out = out_h; J.bias = bv;
        J.xnext = (j < 7) ? x : nullptr;
        J.sh = st[(j + 1) & 1];
        J.fdst = (j == 7) ? S0 : nullptr;
        J.jstep = j;
        return J;
    };
    auto mkSq = [&](int i) {   // squaring i (1..9): A^(2^(i-1)) -> A^(2^i)
        Job J = {};
        if (i == 1) { J.Ah = Wh; J.Al = Wl; J.Bh = WTh; J.Bl = WTl; }
        else {
            __half** s = Pb[i & 1];
            J.Ah = s[0]; J.Al = s[1]; J.Bh = s[2]; J.Bl = s[3];
        }
        __half** d = Pb[(i + 1) & 1];
        J.ph = d[0]; J.pl = d[1]; J.pth = d[2]; J.ptl = d[3];
        return J;
    };
    auto mkScan = [&](int r, float* Sc, float* Sn) {
        Job J = {};
        int pbuf = (4 + r) & 1;
        J.Ah = st[r & 1]; J.Bh = Pb[pbuf][0]; J.Bl = Pb[pbuf][1];
        J.out = Sn; J.addsrc = Sc;
        J.sh = st[(r + 1) & 1];
        J.ashift = -(1 << r) * B_DIM;
        return J;
    };
    auto mkPhase3 = [&](int j) {
        Job J = {};
        J.Ah = st[(j + 1) & 1]; J.Bh = Wh; J.Bl = Wl;
        J.out = out_h; J.fdst = out_silu;
        J.sh = (j < 7) ? st[j & 1] : nullptr;
        J.ashift = (j == 0) ? -B_DIM : 0;
        J.jstep = j;
        return J;
    };

    // phase 1 (8 GEMMs, 2-product)
    for (int j = 0; j < 8; j++)
        gemm_kernel<0,1><<<gg, NTHR, GEMM_SMEM>>>(mkPhase1(j));

    // squarings A^2, A^4, A^8
    for (int i = 1; i <= 3; i++)
        gemm_kernel<1,3><<<gg, NTHR, GEMM_SMEM>>>(mkSq(i));

    // boundary scan interleaved with remaining squarings
    float* Sc = S0;
    float* Sn = S1;
    for (int r = 0; r < 7; r++) {
        gemm_kernel<0,0><<<gg, NTHR, GEMM_SMEM>>>(mkScan(r, Sc, Sn));
        float* tmp = Sc; Sc = Sn; Sn = tmp;
        if (r < 6)
            gemm_kernel<1,3><<<gg, NTHR, GEMM_SMEM>>>(mkSq(r + 4));
    }

    // phase 3: fixup + fused silu
    for (int j = 0; j < 8; j++)
        gemm_kernel<0,2><<<gg, NTHR, GEMM_SMEM>>>(mkPhase3(j));
}